// round 3
// baseline (speedup 1.0000x reference)
#include <cuda_runtime.h>

// WKV (RWKV): B=4, T=4096, H=2048, fp32. Single-pass chunked scan with
// decoupled lookback. Recurrence per channel:
//   a' = ew*a + exp(k)*v ;  b' = ew*b + exp(k) ;  ew const per channel
// Affine => chunk-local sums combine across chunks with eL = ew^CLS.
//
// Each block: chunk of CLS=16 timesteps x 1024 channels (256 float4 lanes).
// Phase 1: stream k,v ONCE, cache exp(k), exp(k)*v in smem, local (a,b) sums.
// Phase 2: publish local sums; decoupled lookback (flag 1=local, 2=inclusive)
//          to obtain the prefix state entering this chunk; publish inclusive.
// Phase 3: replay the exact reference recurrence from smem, emit wkv and the
//          final (a,b).
//
// Total DRAM traffic ~ 256 MB read + 128 MB write (+ ~32 MB L2-resident
// payload) vs 640 MB for the two-pass version.

#define B_      4
#define T_      4096
#define H_      2048
#define H4_     512           // H/4 (float4 lanes)
#define LANES_  256           // threads per block (float4 lanes per block)
#define GROUPS_ 2             // H4_/LANES_
#define CLS_    16            // chunk length (timesteps)
#define NCK_    256           // chunks per chain = T_/CLS_
#define NCH_    8             // chains = B_*GROUPS_
#define NBLK_   (NCK_ * NCH_) // 2048 blocks

// Scratch (__device__ globals; allocation-free rule). ~32 MB, L2-resident.
__device__ float4 g_localA[NBLK_ * LANES_];
__device__ float4 g_localB[NBLK_ * LANES_];
__device__ float4 g_inclA [NBLK_ * LANES_];
__device__ float4 g_inclB [NBLK_ * LANES_];
__device__ int    g_flag  [NBLK_];

__device__ __forceinline__ float4 f4z() { return make_float4(0.f, 0.f, 0.f, 0.f); }
__device__ __forceinline__ float4 f4mul(float4 a, float4 b) {
    return make_float4(a.x * b.x, a.y * b.y, a.z * b.z, a.w * b.w);
}
// a*b + c
__device__ __forceinline__ float4 f4fma(float4 a, float4 b, float4 c) {
    return make_float4(fmaf(a.x, b.x, c.x), fmaf(a.y, b.y, c.y),
                       fmaf(a.z, b.z, c.z), fmaf(a.w, b.w, c.w));
}
__device__ __forceinline__ float4 f4exp(float4 a) {
    return make_float4(__expf(a.x), __expf(a.y), __expf(a.z), __expf(a.w));
}

__global__ void __launch_bounds__(256) wkv_clear() {
    int i = blockIdx.x * blockDim.x + threadIdx.x;
    if (i < NBLK_) g_flag[i] = 0;
}

__global__ void __launch_bounds__(256, 1) wkv_fused(
    const float4* __restrict__ k, const float4* __restrict__ v,
    const float4* __restrict__ td, const float4* __restrict__ tf,
    float4* __restrict__ out, float4* __restrict__ outA,
    float4* __restrict__ outB, int write_ab)
{
    extern __shared__ float4 sm[];               // 128 KB
    float4* smE = sm;                            // exp(k)
    float4* smV = sm + CLS_ * LANES_;            // exp(k)*v

    const int bid   = blockIdx.x;
    const int chain = bid % NCH_;                // lower bid <=> earlier chunk
    const int c     = bid / NCH_;
    const int b     = chain / GROUPS_;
    const int g     = chain % GROUPS_;
    const int lane  = threadIdx.x;
    const int h4    = g * LANES_ + lane;

    const float4 tdv = __ldg(td + h4);
    const float4 ew  = f4exp(make_float4(-__expf(tdv.x), -__expf(tdv.y),
                                         -__expf(tdv.z), -__expf(tdv.w)));
    // eL = ew^CLS_ ; CLS_ = 16 = 2^4 -> 4 squarings
    float4 eL = ew;
    #pragma unroll
    for (int i = 0; i < 4; ++i) eL = f4mul(eL, eL);

    // ---------------- Phase 1: stream chunk once, build smem cache ---------
    const size_t row = ((size_t)b * T_ + (size_t)c * CLS_) * H4_ + h4;
    float4 la = f4z(), lb = f4z();
    #pragma unroll
    for (int t = 0; t < CLS_; ++t) {
        float4 kk  = __ldg(k + row + (size_t)t * H4_);
        float4 vv  = __ldg(v + row + (size_t)t * H4_);
        float4 ek  = f4exp(kk);
        float4 ekv = f4mul(ek, vv);
        smE[t * LANES_ + lane] = ek;
        smV[t * LANES_ + lane] = ekv;
        la = f4fma(ew, la, ekv);
        lb = f4fma(ew, lb, ek);
    }

    // ---------------- Phase 2: publish + decoupled lookback ----------------
    const int pofs = bid * LANES_ + lane;
    float4 Pa = f4z(), Pb = f4z();               // state entering this chunk
    __shared__ int s_f;

    if (c == 0) {
        g_inclA[pofs] = la;
        g_inclB[pofs] = lb;
        __threadfence();
        __syncthreads();
        if (lane == 0) atomicExch(&g_flag[bid], 2);
    } else {
        g_localA[pofs] = la;
        g_localB[pofs] = lb;
        __threadfence();
        __syncthreads();
        if (lane == 0) atomicExch(&g_flag[bid], 1);

        float4 m = make_float4(1.f, 1.f, 1.f, 1.f);
        int j = c - 1;
        for (;;) {
            const int pb = j * NCH_ + chain;     // strictly smaller bid
            if (lane == 0) {
                int f;
                while ((f = atomicAdd(&g_flag[pb], 0)) == 0) __nanosleep(64);
                s_f = f;
            }
            __syncthreads();
            const int f = s_f;
            __syncthreads();                     // s_f reusable next iter
            __threadfence();                     // order payload reads after flag
            const int q = pb * LANES_ + lane;
            if (f == 2) {                        // predecessor inclusive: stop
                float4 ia = __ldcg(&g_inclA[q]);
                float4 ib = __ldcg(&g_inclB[q]);
                Pa = f4fma(m, ia, Pa);
                Pb = f4fma(m, ib, Pb);
                break;
            } else {                             // local only: keep walking
                float4 xa = __ldcg(&g_localA[q]);
                float4 xb = __ldcg(&g_localB[q]);
                Pa = f4fma(m, xa, Pa);
                Pb = f4fma(m, xb, Pb);
                m = f4mul(m, eL);
                --j;                             // chunk 0 always flips to 2
            }
        }
        // inclusive state after this chunk = eL*prefix + local
        g_inclA[pofs] = f4fma(eL, Pa, la);
        g_inclB[pofs] = f4fma(eL, Pb, lb);
        __threadfence();
        __syncthreads();
        if (lane == 0) atomicExch(&g_flag[bid], 2);
    }

    // ---------------- Phase 3: outputs from smem (exact reference order) ---
    const float4 eu = f4exp(__ldg(tf + h4));     // exp(u); exp(u+k)=eu*exp(k)
    float4 a4 = Pa, b4 = Pb;
    #pragma unroll
    for (int t = 0; t < CLS_; ++t) {
        float4 ek  = smE[t * LANES_ + lane];
        float4 ekv = smV[t * LANES_ + lane];
        float4 o;
        o.x = __fdividef(fmaf(eu.x, ekv.x, a4.x), fmaf(eu.x, ek.x, b4.x) + 1e-8f);
        o.y = __fdividef(fmaf(eu.y, ekv.y, a4.y), fmaf(eu.y, ek.y, b4.y) + 1e-8f);
        o.z = __fdividef(fmaf(eu.z, ekv.z, a4.z), fmaf(eu.z, ek.z, b4.z) + 1e-8f);
        o.w = __fdividef(fmaf(eu.w, ekv.w, a4.w), fmaf(eu.w, ek.w, b4.w) + 1e-8f);
        out[row + (size_t)t * H4_] = o;
        a4 = f4fma(ew, a4, ekv);
        b4 = f4fma(ew, b4, ek);
    }

    if (write_ab && c == NCK_ - 1) {             // final carried state
        outA[b * H4_ + h4] = a4;
        outB[b * H4_ + h4] = b4;
    }
}

// ---------------------------------------------------------------------------
// Inputs (metadata order): k, v, time_decay, time_first.
// Output: flattened (output[B,T,H], a[B,H], b[B,H]) when out_size covers it.
// ---------------------------------------------------------------------------
extern "C" void kernel_launch(void* const* d_in, const int* in_sizes, int n_in,
                              void* d_out, int out_size)
{
    const float4* k  = (const float4*)d_in[0];
    const float4* v  = (const float4*)d_in[1];
    const float4* td = (const float4*)d_in[2];
    const float4* tf = (const float4*)d_in[3];

    float4* out = (float4*)d_out;
    const long long main_elems = (long long)B_ * T_ * H_;
    int write_ab = (out_size >= (int)(main_elems + 2LL * B_ * H_)) ? 1 : 0;
    float4* outA = out + main_elems / 4;
    float4* outB = outA + (B_ * H_ / 4);

    const int smem_bytes = 2 * CLS_ * LANES_ * (int)sizeof(float4);  // 128 KB
    cudaFuncSetAttribute(wkv_fused,
                         cudaFuncAttributeMaxDynamicSharedMemorySize,
                         smem_bytes);

    wkv_clear<<<NBLK_ / 256, 256>>>();
    wkv_fused<<<NBLK_, 256, smem_bytes>>>(k, v, td, tf, out, outA, outB,
                                          write_ab);
}

// round 9
// speedup vs baseline: 1.0751x; 1.0751x over previous
#include <cuda_runtime.h>

// WKV (RWKV): B=4, T=4096, H=2048, fp32. Single-pass chunked scan with
// decoupled lookback; per-channel recurrence
//   a' = ew*a + exp(k)*v ;  b' = ew*b + exp(k) ;  ew const per channel.
// Affine => chunk-local sums combine across chunks with eL = ew^CLS.
//
// Design: NO smem payload cache (R3 showed 128 KB smem -> occ 12.5% ->
// 2.7 TB/s). Phase 3 re-reads k,v; those lines were touched microseconds
// earlier by phase 1 of the same block, so the re-read hits L2 (~60-80 MB
// hot footprint << 126 MB L2). smem is 4 B -> multi-block occupancy.
//
// DRAM traffic ~ 256 MB cold read + 128 MB write (+ L2-resident scratch).

#define B_      4
#define T_      4096
#define H_      2048
#define H4_     512           // H/4 (float4 lanes)
#define LANES_  256           // threads per block
#define GROUPS_ 2             // H4_/LANES_
#define CLS_    16            // chunk length (timesteps)
#define NCK_    256           // chunks per chain = T_/CLS_
#define NCH_    8             // chains = B_*GROUPS_
#define NBLK_   (NCK_ * NCH_) // 2048 blocks

// Scratch (__device__ globals; allocation-free rule). ~32 MB, L2-resident.
__device__ float4 g_localA[NBLK_ * LANES_];
__device__ float4 g_localB[NBLK_ * LANES_];
__device__ float4 g_inclA [NBLK_ * LANES_];
__device__ float4 g_inclB [NBLK_ * LANES_];
__device__ int    g_flag  [NBLK_];

__device__ __forceinline__ float4 f4z() { return make_float4(0.f, 0.f, 0.f, 0.f); }
__device__ __forceinline__ float4 f4mul(float4 a, float4 b) {
    return make_float4(a.x * b.x, a.y * b.y, a.z * b.z, a.w * b.w);
}
// a*b + c
__device__ __forceinline__ float4 f4fma(float4 a, float4 b, float4 c) {
    return make_float4(fmaf(a.x, b.x, c.x), fmaf(a.y, b.y, c.y),
                       fmaf(a.z, b.z, c.z), fmaf(a.w, b.w, c.w));
}
__device__ __forceinline__ float4 f4exp(float4 a) {
    return make_float4(__expf(a.x), __expf(a.y), __expf(a.z), __expf(a.w));
}

__global__ void __launch_bounds__(256) wkv_clear() {
    int i = blockIdx.x * blockDim.x + threadIdx.x;
    if (i < NBLK_) g_flag[i] = 0;
}

__global__ void __launch_bounds__(256) wkv_fused(
    const float4* __restrict__ k, const float4* __restrict__ v,
    const float4* __restrict__ td, const float4* __restrict__ tf,
    float4* __restrict__ out, float4* __restrict__ outA,
    float4* __restrict__ outB, int write_ab)
{
    const int bid   = blockIdx.x;
    const int chain = bid % NCH_;                // lower bid <=> earlier chunk
    const int c     = bid / NCH_;
    const int b     = chain / GROUPS_;
    const int g     = chain % GROUPS_;
    const int lane  = threadIdx.x;
    const int h4    = g * LANES_ + lane;

    const float4 tdv = __ldg(td + h4);
    const float4 ew  = f4exp(make_float4(-__expf(tdv.x), -__expf(tdv.y),
                                         -__expf(tdv.z), -__expf(tdv.w)));
    // eL = ew^CLS_ ; CLS_ = 16 = 2^4 -> 4 squarings
    float4 eL = ew;
    #pragma unroll
    for (int i = 0; i < 4; ++i) eL = f4mul(eL, eL);

    // ---------------- Phase 1: stream chunk once, local (a,b) sums ---------
    const size_t row = ((size_t)b * T_ + (size_t)c * CLS_) * H4_ + h4;
    float4 la = f4z(), lb = f4z();
    #pragma unroll 8
    for (int t = 0; t < CLS_; ++t) {
        float4 kk  = __ldg(k + row + (size_t)t * H4_);
        float4 vv  = __ldg(v + row + (size_t)t * H4_);
        float4 ek  = f4exp(kk);
        la = f4fma(ew, la, f4mul(ek, vv));
        lb = f4fma(ew, lb, ek);
    }

    // ---------------- Phase 2: publish + decoupled lookback ----------------
    const int pofs = bid * LANES_ + lane;
    float4 Pa = f4z(), Pb = f4z();               // state entering this chunk
    __shared__ int s_f;

    if (c == 0) {
        g_inclA[pofs] = la;
        g_inclB[pofs] = lb;
        __threadfence();
        __syncthreads();
        if (lane == 0) atomicExch(&g_flag[bid], 2);
    } else {
        g_localA[pofs] = la;
        g_localB[pofs] = lb;
        __threadfence();
        __syncthreads();
        if (lane == 0) atomicExch(&g_flag[bid], 1);

        float4 m = make_float4(1.f, 1.f, 1.f, 1.f);
        int j = c - 1;
        for (;;) {
            const int pb = j * NCH_ + chain;     // strictly smaller bid
            if (lane == 0) {
                int f;
                while ((f = atomicAdd(&g_flag[pb], 0)) == 0) __nanosleep(64);
                s_f = f;
            }
            __syncthreads();
            const int f = s_f;
            __syncthreads();                     // s_f reusable next iter
            __threadfence();                     // order payload reads after flag
            const int q = pb * LANES_ + lane;
            if (f == 2) {                        // predecessor inclusive: stop
                Pa = f4fma(m, __ldcg(&g_inclA[q]), Pa);
                Pb = f4fma(m, __ldcg(&g_inclB[q]), Pb);
                break;
            } else {                             // local only: keep walking
                Pa = f4fma(m, __ldcg(&g_localA[q]), Pa);
                Pb = f4fma(m, __ldcg(&g_localB[q]), Pb);
                m = f4mul(m, eL);
                --j;                             // chunk 0 always flips to 2
            }
        }
        // inclusive state after this chunk = eL*prefix + local
        g_inclA[pofs] = f4fma(eL, Pa, la);
        g_inclB[pofs] = f4fma(eL, Pb, lb);
        __threadfence();
        __syncthreads();
        if (lane == 0) atomicExch(&g_flag[bid], 2);
    }

    // -------- Phase 3: re-read chunk (L2-hot), exact reference order -------
    const float4 eu = f4exp(__ldg(tf + h4));     // exp(u); exp(u+k)=eu*exp(k)
    float4 a4 = Pa, b4 = Pb;
    #pragma unroll 8
    for (int t = 0; t < CLS_; ++t) {
        float4 kk  = __ldcg(k + row + (size_t)t * H4_);
        float4 vv  = __ldcg(v + row + (size_t)t * H4_);
        float4 ek  = f4exp(kk);
        float4 ekv = f4mul(ek, vv);
        float4 o;
        o.x = __fdividef(fmaf(eu.x, ekv.x, a4.x), fmaf(eu.x, ek.x, b4.x) + 1e-8f);
        o.y = __fdividef(fmaf(eu.y, ekv.y, a4.y), fmaf(eu.y, ek.y, b4.y) + 1e-8f);
        o.z = __fdividef(fmaf(eu.z, ekv.z, a4.z), fmaf(eu.z, ek.z, b4.z) + 1e-8f);
        o.w = __fdividef(fmaf(eu.w, ekv.w, a4.w), fmaf(eu.w, ek.w, b4.w) + 1e-8f);
        out[row + (size_t)t * H4_] = o;
        a4 = f4fma(ew, a4, ekv);
        b4 = f4fma(ew, b4, ek);
    }

    if (write_ab && c == NCK_ - 1) {             // final carried state
        outA[b * H4_ + h4] = a4;
        outB[b * H4_ + h4] = b4;
    }
}

// ---------------------------------------------------------------------------
// Inputs (metadata order): k, v, time_decay, time_first.
// Output: flattened (output[B,T,H], a[B,H], b[B,H]) when out_size covers it.
// ---------------------------------------------------------------------------
extern "C" void kernel_launch(void* const* d_in, const int* in_sizes, int n_in,
                              void* d_out, int out_size)
{
    const float4* k  = (const float4*)d_in[0];
    const float4* v  = (const float4*)d_in[1];
    const float4* td = (const float4*)d_in[2];
    const float4* tf = (const float4*)d_in[3];

    float4* out = (float4*)d_out;
    const long long main_elems = (long long)B_ * T_ * H_;
    int write_ab = (out_size >= (int)(main_elems + 2LL * B_ * H_)) ? 1 : 0;
    float4* outA = out + main_elems / 4;
    float4* outB = outA + (B_ * H_ / 4);

    wkv_clear<<<NBLK_ / 256, 256>>>();
    wkv_fused<<<NBLK_, 256>>>(k, v, td, tf, out, outA, outB, write_ab);
}